// round 10
// baseline (speedup 1.0000x reference)
#include <cuda_runtime.h>
#include <cuda_fp16.h>
#include <stdint.h>

// Complex linear folded into one real fp16 GEMM (legacy mma.sync m16n8k16,
// fp32 accum; tcgen05 unreachable: harness targets plain sm_103).
//   X = [x_re | x_im] (N x 1024) fp16 (prepass), W = [[Re,-Im],[Im,Re]] fp16
//   out[n, 0:512] -> out_re, out[n, 512:1024] -> out_im  => (2, N, 512) fp32
// R6..R10: BN=256 (512 thr) halves B smem re-reads; 4-stage ring; fast prepass.

#define M_ROWS 100000
#define KDIM   1024
#define NDIM   1024

#define BM 128
#define BN 256
#define BK 64
#define NT (KDIM / BK)                    // 16
#define TILE_A_BYTES (BM * BK * 2)        // 16384
#define TILE_B_BYTES (BN * BK * 2)        // 32768
#define STAGE_BYTES  (TILE_A_BYTES + TILE_B_BYTES)  // 49152
#define NSTAGE 4
#define SMEM_TOTAL (NSTAGE * STAGE_BYTES) // 196608

// Static scratch (allocation-guard-safe): fp16 X (205MB) and combined W (2MB).
__device__ __half g_X[(size_t)M_ROWS * KDIM];
__device__ __half g_W[(size_t)NDIM * KDIM];

__global__ void build_X_kernel(const float* __restrict__ xre, const float* __restrict__ xim) {
    size_t id = (size_t)blockIdx.x * blockDim.x + threadIdx.x;  // 12.8M threads
    size_t e8 = id * 8;
    const size_t HALF = (size_t)M_ROWS * 512;
    bool is_im = e8 >= HALF;
    size_t off = is_im ? (e8 - HALF) : e8;
    const float* src = (is_im ? xim : xre) + off;
    const float4 v0 = *reinterpret_cast<const float4*>(src);
    const float4 v1 = *reinterpret_cast<const float4*>(src + 4);
    size_t n = off >> 9;
    size_t k = off & 511;
    __half2 h[4];
    h[0] = __floats2half2_rn(v0.x, v0.y);
    h[1] = __floats2half2_rn(v0.z, v0.w);
    h[2] = __floats2half2_rn(v1.x, v1.y);
    h[3] = __floats2half2_rn(v1.z, v1.w);
    *reinterpret_cast<uint4*>(g_X + n * KDIM + (is_im ? 512 : 0) + k) =
        *reinterpret_cast<const uint4*>(h);
}

__global__ void build_W_kernel(const float* __restrict__ Re, const float* __restrict__ Im) {
    int idx = blockIdx.x * blockDim.x + threadIdx.x;   // 1M threads exactly
    int o = idx >> 10;
    int k = idx & 1023;
    float v;
    if (o < 512) v = (k < 512) ? Re[o * 512 + k] : -Im[o * 512 + (k - 512)];
    else         v = (k < 512) ? Im[(o - 512) * 512 + k] : Re[(o - 512) * 512 + (k - 512)];
    g_W[idx] = __float2half_rn(v);
}

__device__ __forceinline__ uint32_t smem_u32(const void* p) {
    uint32_t a;
    asm("{ .reg .u64 t; cvta.to.shared.u64 t, %1; cvt.u32.u64 %0, t; }" : "=r"(a) : "l"(p));
    return a;
}

__device__ __forceinline__ void cp_async16(uint32_t saddr, const void* gptr) {
    asm volatile("cp.async.cg.shared.global [%0], [%1], 16;\n" :: "r"(saddr), "l"(gptr));
}

__device__ __forceinline__ void ldsm_x4(uint32_t* r, uint32_t saddr) {
    asm volatile("ldmatrix.sync.aligned.m8n8.x4.shared.b16 {%0,%1,%2,%3}, [%4];"
                 : "=r"(r[0]), "=r"(r[1]), "=r"(r[2]), "=r"(r[3]) : "r"(saddr));
}

__device__ __forceinline__ void mma_f16(float* c, const uint32_t* a, uint32_t b0, uint32_t b1) {
    asm volatile(
        "mma.sync.aligned.m16n8k16.row.col.f32.f16.f16.f32 "
        "{%0,%1,%2,%3}, {%4,%5,%6,%7}, {%8,%9}, {%0,%1,%2,%3};\n"
        : "+f"(c[0]), "+f"(c[1]), "+f"(c[2]), "+f"(c[3])
        : "r"(a[0]), "r"(a[1]), "r"(a[2]), "r"(a[3]), "r"(b0), "r"(b1));
}

__global__ void __launch_bounds__(512, 1)
cplx_gemm_kernel(float* __restrict__ out)
{
    extern __shared__ char smem[];
    const uint32_t sbase = smem_u32(smem);

    const int n_tile = blockIdx.x;   // 0..3
    const int m_tile = blockIdx.y;   // 0..781
    const int tid  = threadIdx.x;
    const int lane = tid & 31;
    const int warp = tid >> 5;       // 0..15
    const int wm0 = (warp & 3) * 32;   // warp tile: 32 (M) x 64 (N)
    const int wn0 = (warp >> 2) * 64;  // 4 n-groups x 64 = 256
    const int g = lane >> 2;
    const int t = lane & 3;

    // per-lane ldmatrix row/seg components (rows of 128B = 8 x 16B segments)
    const int a_row = (lane & 7) + (((lane >> 3) & 1) << 3);  // + wm0 + mi*16
    const int a_sh  = (lane >> 4) & 1;                        // seg = 2c + a_sh
    const int b_row = (lane & 7) + (((lane >> 4) & 1) << 3);  // + wn0 + np*16
    const int b_sh  = (lane >> 3) & 1;                        // seg = 2c + b_sh

    float acc[2][8][4];
#pragma unroll
    for (int mi = 0; mi < 2; mi++)
#pragma unroll
        for (int ni = 0; ni < 8; ni++)
#pragma unroll
            for (int r = 0; r < 4; r++) acc[mi][ni][r] = 0.0f;

    // ---- loader: cp.async fp16 tiles, rows 128B, seg swizzle j^(row&7) ----
    auto issue = [&](int kt) {
        const int buf = kt % NSTAGE;
        const int k0 = kt * BK;
        const __half* abase = g_X + k0;
        const __half* wbase = g_W + (size_t)(n_tile * BN) * KDIM + k0;
        const uint32_t a_s = sbase + buf * STAGE_BYTES;
        const uint32_t b_s = a_s + TILE_A_BYTES;
        // A: 128 rows x 8 segs = 1024
#pragma unroll
        for (int i = 0; i < 2; i++) {
            int idx = tid + i * 512;
            int row = idx >> 3;
            int j   = idx & 7;
            int grow = m_tile * BM + row;
            if (grow >= M_ROWS) grow = M_ROWS - 1;   // clamp (rows never stored)
            cp_async16(a_s + row * 128 + ((j ^ (row & 7)) << 4),
                       abase + (size_t)grow * KDIM + j * 8);
        }
        // B: 256 rows x 8 segs = 2048
#pragma unroll
        for (int i = 0; i < 4; i++) {
            int idx = tid + i * 512;
            int row = idx >> 3;
            int j   = idx & 7;
            cp_async16(b_s + row * 128 + ((j ^ (row & 7)) << 4),
                       wbase + (size_t)row * KDIM + j * 8);
        }
        asm volatile("cp.async.commit_group;\n" ::: "memory");
    };

    // ---- compute one k-tile (4 chunks of k16) ----
    auto compute = [&](int buf) {
        const uint32_t a_s = sbase + buf * STAGE_BYTES;
        const uint32_t b_s = a_s + TILE_A_BYTES;
#pragma unroll
        for (int c = 0; c < 4; c++) {
            uint32_t A[2][4];
#pragma unroll
            for (int mi = 0; mi < 2; mi++) {
                int row = wm0 + mi * 16 + a_row;
                int seg = (2 * c + a_sh) ^ (row & 7);
                ldsm_x4(A[mi], a_s + row * 128 + (seg << 4));
            }
#pragma unroll
            for (int np = 0; np < 4; np++) {   // pairs of n8-tiles
                uint32_t B[4];
                int row = wn0 + np * 16 + b_row;
                int seg = (2 * c + b_sh) ^ (row & 7);
                ldsm_x4(B, b_s + row * 128 + (seg << 4));
#pragma unroll
                for (int sub = 0; sub < 2; sub++)
#pragma unroll
                    for (int mi = 0; mi < 2; mi++)
                        mma_f16(acc[mi][np * 2 + sub], A[mi], B[sub * 2], B[sub * 2 + 1]);
            }
        }
    };

    // ---- 4-stage pipeline, one barrier per iteration ----
    issue(0);
    issue(1);
    issue(2);
    for (int kt = 0; kt < NT; kt++) {
        if (kt <= NT - 3)      asm volatile("cp.async.wait_group 2;\n" ::: "memory");
        else if (kt == NT - 2) asm volatile("cp.async.wait_group 1;\n" ::: "memory");
        else                   asm volatile("cp.async.wait_group 0;\n" ::: "memory");
        __syncthreads();            // stage kt resident; all warps done with buf (kt-1)%4
        if (kt + 3 < NT) issue(kt + 3);   // overwrites buf (kt-1)%4 — safe after barrier
        compute(kt % NSTAGE);
    }

    // ---- epilogue: scatter into (2, N, 512) ----
#pragma unroll
    for (int mi = 0; mi < 2; mi++) {
        int row = m_tile * BM + wm0 + mi * 16 + g;
        if (row < M_ROWS) {   // M_ROWS % 16 == 0 -> row+8 also valid
#pragma unroll
            for (int ni = 0; ni < 8; ni++) {
                int co = n_tile * BN + wn0 + ni * 8 + (t << 1);
                int half_ = co >> 9;
                int col = co & 511;
                float* op = out + (size_t)half_ * ((size_t)M_ROWS * 512)
                                + (size_t)row * 512 + col;
                *reinterpret_cast<float2*>(op) = make_float2(acc[mi][ni][0], acc[mi][ni][1]);
                *reinterpret_cast<float2*>(op + 8 * 512) = make_float2(acc[mi][ni][2], acc[mi][ni][3]);
            }
        }
    }
}

extern "C" void kernel_launch(void* const* d_in, const int* in_sizes, int n_in,
                              void* d_out, int out_size)
{
    const float* xre = (const float*)d_in[0];
    const float* xim = (const float*)d_in[1];
    const float* Re  = (const float*)d_in[2];
    const float* Im  = (const float*)d_in[3];
    float* out = (float*)d_out;

    cudaFuncSetAttribute(cplx_gemm_kernel,
                         cudaFuncAttributeMaxDynamicSharedMemorySize, SMEM_TOTAL);

    build_X_kernel<<<50000, 256>>>(xre, xim);            // 12.8M threads * 8 elems
    build_W_kernel<<<(NDIM * KDIM) / 256, 256>>>(Re, Im);

    dim3 grid(NDIM / BN, (M_ROWS + BM - 1) / BM);  // (4, 782)
    cplx_gemm_kernel<<<grid, 512, SMEM_TOTAL>>>(out);
}